// round 6
// baseline (speedup 1.0000x reference)
#include <cuda_runtime.h>

// ---------------------------------------------------------------------------
// SinkhornDistance (degenerate loop):
//   out[b] = sum_{i,j} g(xs_i-ys_j, x_i-y_j), g(d1,d2)=c*exp(-10c), c=d1^2+d2^2
// Separable rank-2 => Chebyshev tensor algebra (n=32 nodes):
//   out[b] = <S, Wx K Wy^T> + <K, Wx S Wy^T>,
//   Wx[a,c] = sum_i L_a(xs_i) L_c(x_i),  Wy likewise for (ys, y).
// R5: SINGLE fused kernel. Moments phase on 512 blocks, grid-wide fence via
// atomic counter, blocks 0..7 run the per-batch contraction epilogue.
// Counters and g_W are restored to zero each run => graph-replay safe.
// ---------------------------------------------------------------------------

#define NCH    32
#define NPTS   4096
#define NB     8
#define CHUNK  128
#define NCHUNK (NPTS / CHUNK)          // 32
#define GRID   (NB * 2 * NCHUNK)       // 512
#define TPB    128
#define PPW    (CHUNK / 4)             // 32 points per warp
#define PI     33                      // smem pitch

#define PACK2(out, lo, hi)  asm("mov.b64 %0, {%1, %2};" : "=l"(out) : "f"(lo), "f"(hi))
#define UNPACK2(lo, hi, in) asm("mov.b64 {%0, %1}, %2;" : "=f"(lo), "=f"(hi) : "l"(in))
#define FMA2(out, a, b, c)  asm("fma.rn.f32x2 %0, %1, %2, %3;" : "=l"(out) : "l"(a), "l"(b), "l"(c))

__device__ float g_W[NB * 2 * NCH * NCH];   // zero-init; re-zeroed each run
__device__ unsigned int g_cntA;             // moments arrivals
__device__ unsigned int g_cntB;             // epilogue arrivals

struct MomSh {
    float A[CHUNK * NCH];                   // [pt][a]  (16 KB; doubles as red)
    float B[CHUNK * PI];                    // [pt][c]
    float node[NCH], wt[NCH];
};
struct FinSh {
    float Wx[NCH * PI], Wy[NCH * PI];
    float K [NCH * PI], S [NCH * PI];
    float P [NCH * PI], Q [NCH * PI];
    float red[32];
};

__global__ void __launch_bounds__(TPB) k_fused(
    const float* __restrict__ x,  const float* __restrict__ y,
    const float* __restrict__ xs, const float* __restrict__ ys,
    float* __restrict__ out)
{
    __shared__ __align__(16) union { MomSh m; FinSh f; } sm;

    const int tid   = threadIdx.x;
    const int blk   = blockIdx.x;
    const int chunk = blk & (NCHUNK - 1);
    const int side  = (blk >> 5) & 1;
    const int batch = blk >> 6;

    // ---------------- phase 1: moments ----------------
    if (tid < NCH) {
        float u = (2.0f * tid + 1.0f) / (2.0f * NCH);
        sm.m.node[tid] = cospif(u);
        float s = sinpif(u);
        sm.m.wt[tid] = (tid & 1) ? -s : s;
    }
    __syncthreads();

    const float* A  = side ? ys : xs;       // support coord -> index a
    const float* Bv = side ? y  : x;        // value coord   -> index c
    const int base  = batch * NPTS + chunk * CHUNK;

    // Barycentric Lagrange basis: 256 tasks (128 pts x 2 coords)
    for (int k = tid; k < 2 * CHUNK; k += TPB) {
        const int pt    = k & (CHUNK - 1);
        const int which = k >> 7;
        float v  = which ? Bv[base + pt] : A[base + pt];
        float xi = 2.0f * v - 1.0f;
        float tv[NCH];
        float ssum = 0.0f;
#pragma unroll
        for (int a = 0; a < NCH; a++) {
            float dd = xi - sm.m.node[a];
            dd = copysignf(fmaxf(fabsf(dd), 1e-12f), dd);
            float q = __fdividef(sm.m.wt[a], dd);
            tv[a] = q;
            ssum += q;
        }
        float inv = __fdividef(1.0f, ssum);
        if (which) {
#pragma unroll
            for (int a = 0; a < NCH; a++) sm.m.B[pt * PI + a] = tv[a] * inv;
        } else {
#pragma unroll
            for (int a = 0; a < NCH; a++) sm.m.A[pt * NCH + a] = tv[a] * inv;
        }
    }
    __syncthreads();

    // Outer-product accumulation: warp owns all 32 c-columns, a-rows packed x2
    {
        const int w    = tid >> 5;
        const int lane = tid & 31;
        const int p0   = w * PPW;

        unsigned long long acc[NCH / 2];
#pragma unroll
        for (int a2 = 0; a2 < NCH / 2; a2++) acc[a2] = 0ull;

        for (int i = 0; i < PPW; i++) {
            const int pt = p0 + i;
            float bv = sm.m.B[pt * PI + lane];
            unsigned long long bv2;
            PACK2(bv2, bv, bv);
            const unsigned long long* arow =
                reinterpret_cast<const unsigned long long*>(sm.m.A + pt * NCH);
#pragma unroll
            for (int a2 = 0; a2 < NCH / 2; a2++)
                FMA2(acc[a2], arow[a2], bv2, acc[a2]);
        }

        __syncthreads();
        float* red = sm.m.A;                // 4 warps x 1024 floats overlay
#pragma unroll
        for (int a2 = 0; a2 < NCH / 2; a2++) {
            float lo, hi;
            UNPACK2(lo, hi, acc[a2]);
            red[w * 1024 + (2 * a2)     * NCH + lane] = lo;
            red[w * 1024 + (2 * a2 + 1) * NCH + lane] = hi;
        }
        __syncthreads();

        float* Wp = g_W + (batch * 2 + side) * NCH * NCH;
#pragma unroll
        for (int k = 0; k < 8; k++) {
            int o = tid * 8 + k;
            float v = red[o] + red[1024 + o] + red[2048 + o] + red[3072 + o];
            atomicAdd(&Wp[o], v);           // RED, no return
        }
    }

    __threadfence();
    if (tid == 0) atomicAdd(&g_cntA, 1u);

    if (blk >= NB) return;                  // only blocks 0..7 continue
    const int b = blk;

    // ---------------- grid-wide wait ----------------
    if (tid == 0) {
        while (atomicAdd(&g_cntA, 0u) < (unsigned)GRID) __nanosleep(64);
    }
    __syncthreads();
    __threadfence();                        // acquire: order g_W reads after cnt

    // ---------------- epilogue: contraction for batch b ----------------
    // Load moment matrices (L1-bypassing) and re-zero them for next replay.
    for (int k = tid; k < NCH * NCH; k += TPB) {
        const int a = k >> 5, d = k & 31;
        float wx = __ldcg(&g_W[(b * 2 + 0) * NCH * NCH + k]);
        float wy = __ldcg(&g_W[(b * 2 + 1) * NCH * NCH + k]);
        sm.f.Wx[a * PI + d] = wx;
        sm.f.Wy[a * PI + d] = wy;
        g_W[(b * 2 + 0) * NCH * NCH + k] = 0.0f;
        g_W[(b * 2 + 1) * NCH * NCH + k] = 0.0f;
        // Kernel matrices (nodes identical to phase-1 construction)
        float pa = cospif((2.0f * a + 1.0f) / (2.0f * NCH));
        float pc = cospif((2.0f * d + 1.0f) / (2.0f * NCH));
        float dd = 0.5f * (pa - pc);
        float c2 = dd * dd;
        float e  = expf(-10.0f * c2);
        sm.f.K[a * PI + d] = e;
        sm.f.S[a * PI + d] = c2 * e;
    }
    __syncthreads();

    // P = Wx*K, Q = Wx*S
    for (int e = tid; e < NCH * NCH; e += TPB) {
        const int a = e >> 5, d = e & 31;   // a uniform per warp -> broadcast
        float p = 0.0f, q = 0.0f;
#pragma unroll
        for (int bb = 0; bb < NCH; bb++) {
            float wv = sm.f.Wx[a * PI + bb];
            p = fmaf(wv, sm.f.K[bb * PI + d], p);
            q = fmaf(wv, sm.f.S[bb * PI + d], q);
        }
        sm.f.P[a * PI + d] = p;
        sm.f.Q[a * PI + d] = q;
    }
    __syncthreads();

    // part = S.*(P*Wy^T) + K.*(Q*Wy^T), summed
    float acc = 0.0f;
    for (int e = tid; e < NCH * NCH; e += TPB) {
        const int a = e >> 5, c = e & 31;
        float m = 0.0f, n = 0.0f;
#pragma unroll
        for (int dd = 0; dd < NCH; dd++) {
            float wy = sm.f.Wy[c * PI + dd];
            m = fmaf(sm.f.P[a * PI + dd], wy, m);
            n = fmaf(sm.f.Q[a * PI + dd], wy, n);
        }
        acc += sm.f.S[a * PI + c] * m + sm.f.K[a * PI + c] * n;
    }
#pragma unroll
    for (int off = 16; off > 0; off >>= 1)
        acc += __shfl_xor_sync(0xffffffffu, acc, off);
    if ((tid & 31) == 0) sm.f.red[tid >> 5] = acc;
    __syncthreads();
    if (tid == 0) {
        out[b] = sm.f.red[0] + sm.f.red[1] + sm.f.red[2] + sm.f.red[3];
    }

    // ---------------- counter reset (graph-replay invariant) ----------------
    __threadfence();
    __syncthreads();
    if (tid == 0) {
        unsigned o = atomicAdd(&g_cntB, 1u);
        if (o == NB - 1) {                  // last epilogue block restores state
            atomicExch(&g_cntA, 0u);
            atomicExch(&g_cntB, 0u);
        }
    }
}

extern "C" void kernel_launch(void* const* d_in, const int* in_sizes, int n_in,
                              void* d_out, int out_size)
{
    const float* x  = (const float*)d_in[0];
    const float* y  = (const float*)d_in[1];
    const float* xs = (const float*)d_in[2];
    const float* ys = (const float*)d_in[3];
    float* out = (float*)d_out;
    (void)in_sizes; (void)n_in; (void)out_size;

    k_fused<<<GRID, TPB>>>(x, y, xs, ys, out);
}

// round 7
// speedup vs baseline: 1.1553x; 1.1553x over previous
#include <cuda_runtime.h>

// ---------------------------------------------------------------------------
// SinkhornDistance (degenerate loop):
//   out[b] = sum_{i,j} g(xs_i-ys_j, x_i-y_j), g(d1,d2)=c*exp(-10c), c=d1^2+d2^2
// Separable rank-2 => Chebyshev tensor algebra (n=32 first-kind nodes):
//   out[b] = <S, Wx K Wy^T> + <K, Wx S Wy^T>,
//   Wx[a,c] = sum_i L_a(xs_i) L_c(x_i),  Wy likewise for (ys, y).
// R7: ONE kernel, NO global barrier. 64 blocks per batch; the last block to
// finish a batch (per-batch atomic counter) runs that batch's contraction
// inline. Counters + g_W restored each run => graph-replay safe.
// ---------------------------------------------------------------------------

#define NCH    32
#define NPTS   4096
#define NB     8
#define CHUNK  128
#define NCHUNK (NPTS / CHUNK)          // 32
#define BLK_PER_BATCH (2 * NCHUNK)     // 64
#define GRID   (NB * BLK_PER_BATCH)    // 512
#define TPB    256
#define NWARP  (TPB / 32)              // 8
#define PPW    (CHUNK / NWARP)         // 16 points per warp
#define PI     33                      // smem pitch

#define PACK2(out, lo, hi)  asm("mov.b64 %0, {%1, %2};" : "=l"(out) : "f"(lo), "f"(hi))
#define UNPACK2(lo, hi, in) asm("mov.b64 {%0, %1}, %2;" : "=f"(lo), "=f"(hi) : "l"(in))
#define FMA2(out, a, b, c)  asm("fma.rn.f32x2 %0, %1, %2, %3;" : "=l"(out) : "l"(a), "l"(b), "l"(c))

__device__ float g_W[NB * 2 * NCH * NCH];   // zero-init; re-zeroed by epilogue
__device__ unsigned int g_cnt[NB];          // per-batch arrivals; reset by owner

struct MomSh {
    float A[CHUNK * NCH];                   // [pt][a] 16 KB   (A+B reused as red)
    float B[CHUNK * PI];                    // [pt][c] 16.9 KB
    float node[NCH], wt[NCH];
};
struct FinSh {
    float Wx[NCH * PI], Wy[NCH * PI];
    float K [NCH * PI], S [NCH * PI];
    float P [NCH * PI], Q [NCH * PI];
    float red[NWARP];
};

__global__ void __launch_bounds__(TPB) k_fused(
    const float* __restrict__ x,  const float* __restrict__ y,
    const float* __restrict__ xs, const float* __restrict__ ys,
    float* __restrict__ out)
{
    __shared__ __align__(16) union { MomSh m; FinSh f; } sm;
    __shared__ int s_last;

    const int tid   = threadIdx.x;
    const int blk   = blockIdx.x;
    const int chunk = blk & (NCHUNK - 1);
    const int side  = (blk >> 5) & 1;
    const int batch = blk >> 6;

    // ---------------- phase 1: moment contribution ----------------
    if (tid < NCH) {
        float u = (2.0f * tid + 1.0f) / (2.0f * NCH);
        sm.m.node[tid] = cospif(u);
        float s = sinpif(u);
        sm.m.wt[tid] = (tid & 1) ? -s : s;
    }
    __syncthreads();

    const float* A  = side ? ys : xs;       // support coord -> index a
    const float* Bv = side ? y  : x;        // value coord   -> index c
    const int base  = batch * NPTS + chunk * CHUNK;

    // Barycentric Lagrange basis: 256 tasks = 1 per thread
    {
        const int pt    = tid & (CHUNK - 1);
        const int which = tid >> 7;
        float v  = which ? Bv[base + pt] : A[base + pt];
        float xi = 2.0f * v - 1.0f;
        float tv[NCH];
        float ssum = 0.0f;
#pragma unroll
        for (int a = 0; a < NCH; a++) {
            float dd = xi - sm.m.node[a];
            dd = copysignf(fmaxf(fabsf(dd), 1e-12f), dd);
            float q = __fdividef(sm.m.wt[a], dd);
            tv[a] = q;
            ssum += q;
        }
        float inv = __fdividef(1.0f, ssum);
        if (which) {
#pragma unroll
            for (int a = 0; a < NCH; a++) sm.m.B[pt * PI + a] = tv[a] * inv;
        } else {
#pragma unroll
            for (int a = 0; a < NCH; a++) sm.m.A[pt * NCH + a] = tv[a] * inv;
        }
    }
    __syncthreads();

    // Outer-product: warp owns 16 points x all 32 c-columns; a-rows packed x2
    {
        const int w    = tid >> 5;
        const int lane = tid & 31;
        const int p0   = w * PPW;

        unsigned long long acc[NCH / 2];
#pragma unroll
        for (int a2 = 0; a2 < NCH / 2; a2++) acc[a2] = 0ull;

#pragma unroll 4
        for (int i = 0; i < PPW; i++) {
            const int pt = p0 + i;
            float bv = sm.m.B[pt * PI + lane];          // coalesced
            unsigned long long bv2;
            PACK2(bv2, bv, bv);
            const unsigned long long* arow =
                reinterpret_cast<const unsigned long long*>(sm.m.A + pt * NCH);
#pragma unroll
            for (int a2 = 0; a2 < NCH / 2; a2++)
                FMA2(acc[a2], arow[a2], bv2, acc[a2]);  // LDS.64 broadcast
        }

        __syncthreads();
        float* red = sm.m.A;                // 8 warps x 1024 floats = 32 KB
#pragma unroll
        for (int a2 = 0; a2 < NCH / 2; a2++) {
            float lo, hi;
            UNPACK2(lo, hi, acc[a2]);
            red[w * 1024 + (2 * a2)     * NCH + lane] = lo;
            red[w * 1024 + (2 * a2 + 1) * NCH + lane] = hi;
        }
        __syncthreads();

        float* Wp = g_W + (batch * 2 + side) * NCH * NCH;
#pragma unroll
        for (int k = 0; k < 4; k++) {
            int o = tid * 4 + k;            // o = a*32 + c
            float v = 0.0f;
#pragma unroll
            for (int w2 = 0; w2 < NWARP; w2++) v += red[w2 * 1024 + o];
            atomicAdd(&Wp[o], v);           // RED, no return
        }
    }

    // ---------------- per-batch last-block election ----------------
    __threadfence();
    __syncthreads();                        // all REDs of this block issued
    if (tid == 0) {
        unsigned prev = atomicAdd(&g_cnt[batch], 1u);
        s_last = (prev == BLK_PER_BATCH - 1);
    }
    __syncthreads();
    if (!s_last) return;

    const int b = batch;
    __threadfence();                        // acquire pairing for g_W reads

    // ---------------- epilogue: contraction for batch b ----------------
    for (int k = tid; k < NCH * NCH; k += TPB) {
        const int a = k >> 5, d = k & 31;
        float wx = __ldcg(&g_W[(b * 2 + 0) * NCH * NCH + k]);
        float wy = __ldcg(&g_W[(b * 2 + 1) * NCH * NCH + k]);
        sm.f.Wx[a * PI + d] = wx;
        sm.f.Wy[a * PI + d] = wy;
        g_W[(b * 2 + 0) * NCH * NCH + k] = 0.0f;   // restore for next replay
        g_W[(b * 2 + 1) * NCH * NCH + k] = 0.0f;
        float pa = cospif((2.0f * a + 1.0f) / (2.0f * NCH));
        float pc = cospif((2.0f * d + 1.0f) / (2.0f * NCH));
        float dd = 0.5f * (pa - pc);
        float c2 = dd * dd;
        float e  = expf(-10.0f * c2);
        sm.f.K[a * PI + d] = e;
        sm.f.S[a * PI + d] = c2 * e;
    }
    __syncthreads();

    // P = Wx*K, Q = Wx*S
    for (int e = tid; e < NCH * NCH; e += TPB) {
        const int a = e >> 5, d = e & 31;
        float p = 0.0f, q = 0.0f;
#pragma unroll
        for (int bb = 0; bb < NCH; bb++) {
            float wv = sm.f.Wx[a * PI + bb];
            p = fmaf(wv, sm.f.K[bb * PI + d], p);
            q = fmaf(wv, sm.f.S[bb * PI + d], q);
        }
        sm.f.P[a * PI + d] = p;
        sm.f.Q[a * PI + d] = q;
    }
    __syncthreads();

    // sum of S.*(P*Wy^T) + K.*(Q*Wy^T)
    float acc = 0.0f;
    for (int e = tid; e < NCH * NCH; e += TPB) {
        const int a = e >> 5, c = e & 31;
        float m = 0.0f, n = 0.0f;
#pragma unroll
        for (int dd = 0; dd < NCH; dd++) {
            float wy = sm.f.Wy[c * PI + dd];
            m = fmaf(sm.f.P[a * PI + dd], wy, m);
            n = fmaf(sm.f.Q[a * PI + dd], wy, n);
        }
        acc += sm.f.S[a * PI + c] * m + sm.f.K[a * PI + c] * n;
    }
#pragma unroll
    for (int off = 16; off > 0; off >>= 1)
        acc += __shfl_xor_sync(0xffffffffu, acc, off);
    if ((tid & 31) == 0) sm.f.red[tid >> 5] = acc;
    __syncthreads();

    if (tid == 0) {
        float v = 0.0f;
#pragma unroll
        for (int w2 = 0; w2 < NWARP; w2++) v += sm.f.red[w2];
        out[b] = v;
        atomicExch(&g_cnt[b], 0u);          // restore counter for next replay
    }
}

extern "C" void kernel_launch(void* const* d_in, const int* in_sizes, int n_in,
                              void* d_out, int out_size)
{
    const float* x  = (const float*)d_in[0];
    const float* y  = (const float*)d_in[1];
    const float* xs = (const float*)d_in[2];
    const float* ys = (const float*)d_in[3];
    float* out = (float*)d_out;
    (void)in_sizes; (void)n_in; (void)out_size;

    k_fused<<<GRID, TPB>>>(x, y, xs, ys, out);
}

// round 8
// speedup vs baseline: 1.2947x; 1.1206x over previous
#include <cuda_runtime.h>

// ---------------------------------------------------------------------------
// SinkhornDistance (degenerate loop):
//   out[b] = sum_{i,j} g(xs_i-ys_j, x_i-y_j), g(d1,d2)=c*exp(-10c), c=d1^2+d2^2
// Separable rank-2 => Chebyshev tensor algebra (n=32 first-kind nodes):
//   out[b] = <S, Wx K Wy^T> + <K, Wx S Wy^T>,
//   Wx[a,c] = sum_i L_a(xs_i) L_c(x_i),  Wy likewise for (ys, y).
// R8: ONE kernel, per-batch last-block epilogue (R7) + XOR-swizzled 64-bit
// A-basis storage. R7's A stores were 32-way bank-conflicted (pitch-32 rows);
// the swizzle makes stores 2-way and keeps GEMM reads broadcast + aligned.
// ---------------------------------------------------------------------------

#define NCH    32
#define NPTS   4096
#define NB     8
#define CHUNK  128
#define NCHUNK (NPTS / CHUNK)          // 32
#define BLK_PER_BATCH (2 * NCHUNK)     // 64
#define GRID   (NB * BLK_PER_BATCH)    // 512
#define TPB    256
#define NWARP  (TPB / 32)              // 8
#define PPW    (CHUNK / NWARP)         // 16 points per warp
#define PI     33                      // B pitch (floats), conflict-free

#define PACK2(out, lo, hi)  asm("mov.b64 %0, {%1, %2};" : "=l"(out) : "f"(lo), "f"(hi))
#define UNPACK2(lo, hi, in) asm("mov.b64 {%0, %1}, %2;" : "=f"(lo), "=f"(hi) : "l"(in))
#define FMA2(out, a, b, c)  asm("fma.rn.f32x2 %0, %1, %2, %3;" : "=l"(out) : "l"(a), "l"(b), "l"(c))

__device__ float g_W[NB * 2 * NCH * NCH];   // zero-init; re-zeroed by epilogue
__device__ unsigned int g_cnt[NB];          // per-batch arrivals; reset by owner

struct MomSh {
    unsigned long long A64[CHUNK * 16];     // [pt][swizzled a-pair], 16 KB
    float B[CHUNK * PI];                    // [pt][c]
    float node[NCH], wt[NCH];
};
struct FinSh {
    float Wx[NCH * PI], Wy[NCH * PI];
    float K [NCH * PI], S [NCH * PI];
    float P [NCH * PI], Q [NCH * PI];
    float red[NWARP];
};

__global__ void __launch_bounds__(TPB) k_fused(
    const float* __restrict__ x,  const float* __restrict__ y,
    const float* __restrict__ xs, const float* __restrict__ ys,
    float* __restrict__ out)
{
    __shared__ __align__(16) union { MomSh m; FinSh f; } sm;
    __shared__ int s_last;

    const int tid   = threadIdx.x;
    const int blk   = blockIdx.x;
    const int chunk = blk & (NCHUNK - 1);
    const int side  = (blk >> 5) & 1;
    const int batch = blk >> 6;

    // ---------------- phase 1: moment contribution ----------------
    if (tid < NCH) {
        float u = (2.0f * tid + 1.0f) / (2.0f * NCH);
        sm.m.node[tid] = cospif(u);
        float s = sinpif(u);
        sm.m.wt[tid] = (tid & 1) ? -s : s;
    }
    __syncthreads();

    const float* A  = side ? ys : xs;       // support coord -> index a
    const float* Bv = side ? y  : x;        // value coord   -> index c
    const int base  = batch * NPTS + chunk * CHUNK;

    // Barycentric Lagrange basis: 256 tasks = 1 per thread
    {
        const int pt    = tid & (CHUNK - 1);
        const int which = tid >> 7;
        float v  = which ? Bv[base + pt] : A[base + pt];
        float xi = 2.0f * v - 1.0f;
        float tv[NCH];
        float ssum = 0.0f;
#pragma unroll
        for (int a = 0; a < NCH; a++) {
            float dd = xi - sm.m.node[a];
            dd = copysignf(fmaxf(fabsf(dd), 1e-12f), dd);
            float q = __fdividef(sm.m.wt[a], dd);
            tv[a] = q;
            ssum += q;
        }
        float inv = __fdividef(1.0f, ssum);
        if (which) {
#pragma unroll
            for (int a = 0; a < NCH; a++) sm.m.B[pt * PI + a] = tv[a] * inv;
        } else {
            const int sw = pt & 15;
#pragma unroll
            for (int a2 = 0; a2 < 16; a2++) {
                unsigned long long pr;
                PACK2(pr, tv[2 * a2] * inv, tv[2 * a2 + 1] * inv);
                sm.m.A64[pt * 16 + (a2 ^ sw)] = pr;   // 2-way conflict store
            }
        }
    }
    __syncthreads();

    // Outer-product: warp owns 16 points x all 32 c-columns; a-rows packed x2
    {
        const int w    = tid >> 5;
        const int lane = tid & 31;
        const int p0   = w * PPW;               // multiple of 16 -> sw == i

        unsigned long long acc[NCH / 2];
#pragma unroll
        for (int a2 = 0; a2 < NCH / 2; a2++) acc[a2] = 0ull;

#pragma unroll 4
        for (int i = 0; i < PPW; i++) {
            const int pt = p0 + i;
            float bv = sm.m.B[pt * PI + lane];              // coalesced
            unsigned long long bv2;
            PACK2(bv2, bv, bv);
            const unsigned long long* arow = sm.m.A64 + pt * 16;
#pragma unroll
            for (int a2 = 0; a2 < NCH / 2; a2++)
                FMA2(acc[a2], arow[a2 ^ i], bv2, acc[a2]);  // LDS.64 broadcast
        }

        __syncthreads();
        float* red = reinterpret_cast<float*>(sm.m.A64);    // 8x1024 floats
#pragma unroll
        for (int a2 = 0; a2 < NCH / 2; a2++) {
            float lo, hi;
            UNPACK2(lo, hi, acc[a2]);
            red[w * 1024 + (2 * a2)     * NCH + lane] = lo; // conflict-free
            red[w * 1024 + (2 * a2 + 1) * NCH + lane] = hi;
        }
        __syncthreads();

        float* Wp = g_W + (batch * 2 + side) * NCH * NCH;
#pragma unroll
        for (int k = 0; k < 4; k++) {
            int o = tid + 256 * k;              // coalesced, conflict-free
            float v = 0.0f;
#pragma unroll
            for (int w2 = 0; w2 < NWARP; w2++) v += red[w2 * 1024 + o];
            atomicAdd(&Wp[o], v);               // RED, no return
        }
    }

    // ---------------- per-batch last-block election ----------------
    __threadfence();
    __syncthreads();
    if (tid == 0) {
        unsigned prev = atomicAdd(&g_cnt[batch], 1u);
        s_last = (prev == BLK_PER_BATCH - 1);
    }
    __syncthreads();
    if (!s_last) return;

    const int b = batch;
    __threadfence();                            // acquire for g_W reads

    // ---------------- epilogue: contraction for batch b ----------------
    for (int k = tid; k < NCH * NCH; k += TPB) {
        const int a = k >> 5, d = k & 31;
        float wx = __ldcg(&g_W[(b * 2 + 0) * NCH * NCH + k]);
        float wy = __ldcg(&g_W[(b * 2 + 1) * NCH * NCH + k]);
        sm.f.Wx[a * PI + d] = wx;
        sm.f.Wy[a * PI + d] = wy;
        g_W[(b * 2 + 0) * NCH * NCH + k] = 0.0f;   // restore for next replay
        g_W[(b * 2 + 1) * NCH * NCH + k] = 0.0f;
        float pa = cospif((2.0f * a + 1.0f) / (2.0f * NCH));
        float pc = cospif((2.0f * d + 1.0f) / (2.0f * NCH));
        float dd = 0.5f * (pa - pc);
        float c2 = dd * dd;
        float e  = expf(-10.0f * c2);
        sm.f.K[a * PI + d] = e;
        sm.f.S[a * PI + d] = c2 * e;
    }
    __syncthreads();

    // P = Wx*K, Q = Wx*S
    for (int e = tid; e < NCH * NCH; e += TPB) {
        const int a = e >> 5, d = e & 31;
        float p = 0.0f, q = 0.0f;
#pragma unroll
        for (int bb = 0; bb < NCH; bb++) {
            float wv = sm.f.Wx[a * PI + bb];
            p = fmaf(wv, sm.f.K[bb * PI + d], p);
            q = fmaf(wv, sm.f.S[bb * PI + d], q);
        }
        sm.f.P[a * PI + d] = p;
        sm.f.Q[a * PI + d] = q;
    }
    __syncthreads();

    // sum of S.*(P*Wy^T) + K.*(Q*Wy^T)
    float acc = 0.0f;
    for (int e = tid; e < NCH * NCH; e += TPB) {
        const int a = e >> 5, c = e & 31;
        float m = 0.0f, n = 0.0f;
#pragma unroll
        for (int dd = 0; dd < NCH; dd++) {
            float wy = sm.f.Wy[c * PI + dd];
            m = fmaf(sm.f.P[a * PI + dd], wy, m);
            n = fmaf(sm.f.Q[a * PI + dd], wy, n);
        }
        acc += sm.f.S[a * PI + c] * m + sm.f.K[a * PI + c] * n;
    }
#pragma unroll
    for (int off = 16; off > 0; off >>= 1)
        acc += __shfl_xor_sync(0xffffffffu, acc, off);
    if ((tid & 31) == 0) sm.f.red[tid >> 5] = acc;
    __syncthreads();

    if (tid == 0) {
        float v = 0.0f;
#pragma unroll
        for (int w2 = 0; w2 < NWARP; w2++) v += sm.f.red[w2];
        out[b] = v;
        atomicExch(&g_cnt[b], 0u);              // restore counter for replay
    }
}

extern "C" void kernel_launch(void* const* d_in, const int* in_sizes, int n_in,
                              void* d_out, int out_size)
{
    const float* x  = (const float*)d_in[0];
    const float* y  = (const float*)d_in[1];
    const float* xs = (const float*)d_in[2];
    const float* ys = (const float*)d_in[3];
    float* out = (float*)d_out;
    (void)in_sizes; (void)n_in; (void)out_size;

    k_fused<<<GRID, TPB>>>(x, y, xs, ys, out);
}